// round 1
// baseline (speedup 1.0000x reference)
#include <cuda_runtime.h>
#include <stdint.h>

#define N_PTS   50000
#define B_ROWS  512
#define E_DIM   16
#define KSEL    20
#define TILE    256
#define G_ROWS  8
#define HID     64
#define FULLM   0xffffffffu

__device__ float g_norm[2][N_PTS];
__device__ float g_feats[B_ROWS][8];

static __device__ __forceinline__ float finf() { return __int_as_float(0x7f800000); }

// ---------------------------------------------------------------------------
// Kernel 0: candidate squared norms for both embedding sets
// ---------------------------------------------------------------------------
__global__ void norms_kernel(const float* __restrict__ emb0,
                             const float* __restrict__ emb1, int n) {
    int i = blockIdx.x * blockDim.x + threadIdx.x;
    if (i >= n) return;
    float s0 = 0.f, s1 = 0.f;
    const float4* p0 = reinterpret_cast<const float4*>(emb0 + (size_t)i * E_DIM);
    const float4* p1 = reinterpret_cast<const float4*>(emb1 + (size_t)i * E_DIM);
#pragma unroll
    for (int q = 0; q < 4; q++) {
        float4 a = p0[q];
        s0 += a.x * a.x + a.y * a.y + a.z * a.z + a.w * a.w;
        float4 b = p1[q];
        s1 += b.x * b.x + b.y * b.y + b.z * b.z + b.w * b.w;
    }
    g_norm[0][i] = s0;
    g_norm[1][i] = s1;
}

// ---------------------------------------------------------------------------
// Kernel 1: fused distance + top-20 + feature computation
//   grid = (B/G_ROWS, 2 sets), block = 256 threads
//   Phase A: all 256 threads compute s = |e|^2 - 2 a_r . e for 8 rows -> smem
//   Phase B: warp w maintains the top-20 (smallest s) for row w,
//            distributed across lanes 0..19 (sorted ascending)
// ---------------------------------------------------------------------------
__global__ __launch_bounds__(256, 1)
void knn_kernel(const float* __restrict__ emb0, const float* __restrict__ emb1,
                const float* __restrict__ rctx0, const float* __restrict__ rctx1,
                const int* __restrict__ idx0, const int* __restrict__ idx1,
                int n) {
    const int set = blockIdx.y;
    const float* __restrict__ emb  = set ? emb1 : emb0;
    const float* __restrict__ rctx = set ? rctx1 : rctx0;
    const int*   __restrict__ idxp = set ? idx1 : idx0;
    const float* __restrict__ nrmp = set ? g_norm[1] : g_norm[0];

    const int rowbase = blockIdx.x * G_ROWS;
    const int tid  = threadIdx.x;
    const int lane = tid & 31;
    const int w    = tid >> 5;            // warp id == local row id

    // ---- load the 8 query vectors into registers (uniform across block) ----
    float q[G_ROWS][E_DIM];
    int   selfr[G_ROWS];
#pragma unroll
    for (int r = 0; r < G_ROWS; r++) {
        int si = idxp[rowbase + r];
        selfr[r] = si;
        const float4* qp = reinterpret_cast<const float4*>(emb + (size_t)si * E_DIM);
#pragma unroll
        for (int c = 0; c < 4; c++) {
            float4 v = qp[c];
            q[r][4 * c + 0] = v.x; q[r][4 * c + 1] = v.y;
            q[r][4 * c + 2] = v.z; q[r][4 * c + 3] = v.w;
        }
    }
    const int myself = selfr[w];

    __shared__ float sbuf[2][TILE][9];   // pad 9 -> conflict-free rows & cols

    // ---- warp-distributed top-k state ----
    float kval  = finf();                // lane i (i<20): i-th smallest s
    int   kidx  = -1;
    float thresh = finf();               // current 20th smallest (uniform)

    const int ntiles = (n + TILE - 1) / TILE;

    // ---- preload tile 0 ----
    float ec[E_DIM], en[E_DIM];
    float ecn = 0.f, enn = 0.f;
    bool  vc, vn;
    {
        int j = tid;
        vc = (j < n);
        if (vc) {
            const float4* ep = reinterpret_cast<const float4*>(emb + (size_t)j * E_DIM);
#pragma unroll
            for (int c = 0; c < 4; c++) {
                float4 v = ep[c];
                ec[4 * c + 0] = v.x; ec[4 * c + 1] = v.y;
                ec[4 * c + 2] = v.z; ec[4 * c + 3] = v.w;
            }
            ecn = nrmp[j];
        } else {
#pragma unroll
            for (int k = 0; k < E_DIM; k++) ec[k] = 0.f;
        }
    }

    for (int t = 0; t < ntiles; t++) {
        const int buf = t & 1;

        // -------- prefetch next tile into en[] (before compute) --------
        {
            int j = (t + 1) * TILE + tid;
            vn = (j < n) && (t + 1 < ntiles);
            if (vn) {
                const float4* ep = reinterpret_cast<const float4*>(emb + (size_t)j * E_DIM);
#pragma unroll
                for (int c = 0; c < 4; c++) {
                    float4 v = ep[c];
                    en[4 * c + 0] = v.x; en[4 * c + 1] = v.y;
                    en[4 * c + 2] = v.z; en[4 * c + 3] = v.w;
                }
                enn = nrmp[j];
            }
        }

        // -------- Phase A: 8 dot products per thread --------
        float acc[G_ROWS];
#pragma unroll
        for (int r = 0; r < G_ROWS; r++) acc[r] = 0.f;
#pragma unroll
        for (int k = 0; k < E_DIM; k++) {
            float ek = ec[k];
#pragma unroll
            for (int r = 0; r < G_ROWS; r++)
                acc[r] = fmaf(q[r][k], ek, acc[r]);
        }
#pragma unroll
        for (int r = 0; r < G_ROWS; r++) {
            float s = vc ? fmaf(-2.f, acc[r], ecn) : finf();
            sbuf[buf][tid][r] = s;
        }

        __syncthreads();

        // -------- Phase B: warp w scans its row's column --------
        const int base = t * TILE;
#pragma unroll
        for (int sIt = 0; sIt < TILE / 32; sIt++) {
            int tt = lane + 32 * sIt;
            float v = sbuf[buf][tt][w];
            int   j = base + tt;
            bool ok = (v < thresh) && (j != myself);
            unsigned m = __ballot_sync(FULLM, ok);
            while (m) {
                int src = __ffs(m) - 1;
                m &= m - 1;
                float bv = __shfl_sync(FULLM, v, src);
                int   bj = __shfl_sync(FULLM, j, src);
                if (bv < thresh) {
                    float pv = __shfl_up_sync(FULLM, kval, 1);
                    int   pj = __shfl_up_sync(FULLM, kidx, 1);
                    if (lane < KSEL && bv < kval) {
                        if (lane == 0 || bv >= pv) { kval = bv; kidx = bj; }
                        else                        { kval = pv; kidx = pj; }
                    }
                    thresh = __shfl_sync(FULLM, kval, KSEL - 1);
                }
            }
        }

        // rotate prefetch -> current
        vc = vn; ecn = enn;
#pragma unroll
        for (int k = 0; k < E_DIM; k++) ec[k] = en[k];
    }

    // -------- features for row (rowbase + w), per warp --------
    const int row = rowbase + w;
    float na = nrmp[myself];

    float wgt = 0.f, sel = 0.f;
    if (lane < KSEL) {
        float d2 = fmaxf(kval + na, 0.f);
        float sim = sqrtf(d2) + 0.001f;
        wgt = expf(-sim);
        sel = rctx[(size_t)row * n + kidx];
    }
    float sw = wgt, ssw = sel * wgt, ss = sel, ss2 = sel * sel;
#pragma unroll
    for (int off = 16; off; off >>= 1) {
        sw  += __shfl_xor_sync(FULLM, sw,  off);
        ssw += __shfl_xor_sync(FULLM, ssw, off);
        ss  += __shfl_xor_sync(FULLM, ss,  off);
        ss2 += __shfl_xor_sync(FULLM, ss2, off);
    }
    if (lane == 0) {
        float f1 = sw;
        float f2 = ssw / sw;
        float var = (ss2 - ss * ss / (float)KSEL) / (float)(KSEL - 1);
        float f3 = sqrtf(fmaxf(var, 0.f));
        g_feats[row][0 + set] = f1;
        g_feats[row][2 + set] = f2;
        g_feats[row][4 + set] = f3;
    }
}

// ---------------------------------------------------------------------------
// Kernel 2: tiny MLP  (feats[8] -> relu(64) -> mean,std)
// ---------------------------------------------------------------------------
__global__ void mlp_kernel(const float* __restrict__ mean_in,
                           const float* __restrict__ std_in,
                           const float* __restrict__ W1,
                           const float* __restrict__ b1,
                           const float* __restrict__ Wm,
                           const float* __restrict__ bm,
                           const float* __restrict__ Ws,
                           const float* __restrict__ bs,
                           float* __restrict__ out, int Bn) {
    int r = blockIdx.x * blockDim.x + threadIdx.x;
    if (r >= Bn) return;
    float f[8];
#pragma unroll
    for (int i = 0; i < 6; i++) f[i] = g_feats[r][i];
    f[6] = mean_in[r];
    f[7] = std_in[r];
    float m = bm[0], sd = bs[0];
    for (int j = 0; j < HID; j++) {
        float h = b1[j];
#pragma unroll
        for (int i = 0; i < 8; i++) h = fmaf(f[i], W1[i * HID + j], h);
        h = fmaxf(h, 0.f);
        m  = fmaf(h, Wm[j], m);
        sd = fmaf(h, Ws[j], sd);
    }
    out[r]      = m;
    out[Bn + r] = sd;
}

// ---------------------------------------------------------------------------
extern "C" void kernel_launch(void* const* d_in, const int* in_sizes, int n_in,
                              void* d_out, int out_size) {
    const float* emb0    = (const float*)d_in[0];
    const float* emb1    = (const float*)d_in[1];
    const float* rctx0   = (const float*)d_in[2];
    const float* rctx1   = (const float*)d_in[3];
    const int*   idx0    = (const int*)  d_in[4];
    const int*   idx1    = (const int*)  d_in[5];
    const float* mean_in = (const float*)d_in[6];
    const float* std_in  = (const float*)d_in[7];
    const float* W1      = (const float*)d_in[8];
    const float* b1      = (const float*)d_in[9];
    const float* Wm      = (const float*)d_in[10];
    const float* bm      = (const float*)d_in[11];
    const float* Ws      = (const float*)d_in[12];
    const float* bs      = (const float*)d_in[13];

    int n  = in_sizes[0] / E_DIM;   // 50000
    int Bn = in_sizes[4];           // 512

    norms_kernel<<<(n + 255) / 256, 256>>>(emb0, emb1, n);

    dim3 grid(Bn / G_ROWS, 2);
    knn_kernel<<<grid, 256>>>(emb0, emb1, rctx0, rctx1, idx0, idx1, n);

    mlp_kernel<<<(Bn + 255) / 256, 256>>>(mean_in, std_in, W1, b1, Wm, bm, Ws, bs,
                                          (float*)d_out, Bn);
}

// round 2
// speedup vs baseline: 1.0996x; 1.0996x over previous
#include <cuda_runtime.h>
#include <stdint.h>

#define N_PTS   50000
#define B_ROWS  512
#define E_DIM   16
#define KSEL    20
#define TILE    256
#define G_ROWS  8
#define HID     64
#define FULLM   0xffffffffu

typedef unsigned long long ull;

__device__ float g_feats[B_ROWS][8];

static __device__ __forceinline__ float finf() { return __int_as_float(0x7f800000); }

// ---- packed f32x2 helpers (PTX-only; ptxas never auto-fuses these) ----
static __device__ __forceinline__ ull pk2(float lo, float hi) {
    ull r; asm("mov.b64 %0,{%1,%2};" : "=l"(r) : "f"(lo), "f"(hi)); return r;
}
static __device__ __forceinline__ void upk2(ull v, float& lo, float& hi) {
    asm("mov.b64 {%0,%1},%2;" : "=f"(lo), "=f"(hi) : "l"(v));
}
static __device__ __forceinline__ ull fma2(ull a, ull b, ull c) {
    ull d; asm("fma.rn.f32x2 %0,%1,%2,%3;" : "=l"(d) : "l"(a), "l"(b), "l"(c)); return d;
}
static __device__ __forceinline__ ull add2(ull a, ull b) {
    ull d; asm("add.rn.f32x2 %0,%1,%2;" : "=l"(d) : "l"(a), "l"(b)); return d;
}

// ---------------------------------------------------------------------------
// Fused distance + top-20 + feature kernel.
//   grid = (B/G_ROWS, 2 sets), block = 256 threads (8 warps), occ 1.
//   Phase A: thread tid computes s = |e_j|^2 - 2 a_r . e_j  (j = tile base+tid)
//            for all 8 rows using packed f32x2 FMA; norms folded in. -> smem
//   Phase B: warp w owns row w; hit-mask + redux fast path, warp-distributed
//            sorted top-20 insert on the rare hits.
// ---------------------------------------------------------------------------
__global__ __launch_bounds__(256, 1)
void knn_kernel(const float* __restrict__ emb0, const float* __restrict__ emb1,
                const float* __restrict__ rctx0, const float* __restrict__ rctx1,
                const int* __restrict__ idx0, const int* __restrict__ idx1,
                int n) {
    const int set = blockIdx.y;
    const float* __restrict__ emb  = set ? emb1 : emb0;
    const float* __restrict__ rctx = set ? rctx1 : rctx0;
    const int*   __restrict__ idxp = set ? idx1 : idx0;

    const int rowbase = blockIdx.x * G_ROWS;
    const int tid  = threadIdx.x;
    const int lane = tid & 31;
    const int w    = tid >> 5;              // warp id == local row id

    // ---- load the 8 query vectors, pre-scaled by -2, packed into f32x2 ----
    ull   q2[G_ROWS][E_DIM / 2];
    int   selfr[G_ROWS];
    float na = 0.f;                         // |a|^2 for this warp's row
#pragma unroll
    for (int r = 0; r < G_ROWS; r++) {
        int si = idxp[rowbase + r];
        selfr[r] = si;
        const float4* qp = reinterpret_cast<const float4*>(emb + (size_t)si * E_DIM);
#pragma unroll
        for (int c = 0; c < 4; c++) {
            float4 v = qp[c];
            if (r == w) na += v.x * v.x + v.y * v.y + v.z * v.z + v.w * v.w;
            q2[r][2 * c + 0] = pk2(-2.f * v.x, -2.f * v.y);
            q2[r][2 * c + 1] = pk2(-2.f * v.z, -2.f * v.w);
        }
    }
    const int myself = selfr[w];

    __shared__ float sbuf[2][TILE][9];      // pad 9 -> conflict-free both ways

    // ---- warp-distributed top-k state (lanes 0..19, ascending s) ----
    float kval   = finf();
    int   kidx   = -1;
    float thresh = finf();

    const int ntiles = (n + TILE - 1) / TILE;   // 196 (even)

    ull eA[8], eB[8];

    auto loadTile = [&](int t, ull* e2) {
        int j = t * TILE + tid;
        if (j < n) {
            const ulonglong2* ep =
                reinterpret_cast<const ulonglong2*>(emb + (size_t)j * E_DIM);
            ulonglong2 a = ep[0], b = ep[1], c = ep[2], d = ep[3];
            e2[0] = a.x; e2[1] = a.y; e2[2] = b.x; e2[3] = b.y;
            e2[4] = c.x; e2[5] = c.y; e2[6] = d.x; e2[7] = d.y;
        }
    };

    auto phaseA = [&](int t, int buf, ull* e2) {
        bool valid = (t * TILE + tid) < n;
        // candidate norm: two chains to cap serial depth
        ull nA = pk2(0.f, 0.f), nB = pk2(0.f, 0.f);
#pragma unroll
        for (int c = 0; c < 8; c += 2) {
            nA = fma2(e2[c], e2[c], nA);
            nB = fma2(e2[c + 1], e2[c + 1], nB);
        }
        ull nrm2 = add2(nA, nB);            // (nlo, nhi); final |e|^2 = nlo+nhi
        ull acc[G_ROWS];
#pragma unroll
        for (int r = 0; r < G_ROWS; r++) acc[r] = nrm2;
#pragma unroll
        for (int c = 0; c < 8; c++) {
            ull ec = e2[c];
#pragma unroll
            for (int r = 0; r < G_ROWS; r++)
                acc[r] = fma2(q2[r][c], ec, acc[r]);
        }
#pragma unroll
        for (int r = 0; r < G_ROWS; r++) {
            float lo, hi; upk2(acc[r], lo, hi);
            float s = valid ? (lo + hi) : finf();   // |e|^2 - 2 a.e
            sbuf[buf][tid][r] = s;
        }
    };

    auto phaseB = [&](int t, int buf) {
        const int base = t * TILE;
        float v[8];
#pragma unroll
        for (int i = 0; i < 8; i++) v[i] = sbuf[buf][lane + 32 * i][w];
        unsigned hm = 0;
#pragma unroll
        for (int i = 0; i < 8; i++) {
            int j = base + lane + 32 * i;
            if (v[i] < thresh && j != myself) hm |= (1u << i);
        }
        unsigned red = __reduce_or_sync(FULLM, hm);
        while (red) {
            int i = __ffs(red) - 1; red &= red - 1;
            unsigned m = __ballot_sync(FULLM, (hm >> i) & 1u);
            float vi = v[i];
            int   ji = base + lane + 32 * i;
            while (m) {
                int src = __ffs(m) - 1; m &= m - 1;
                float bv = __shfl_sync(FULLM, vi, src);
                int   bj = __shfl_sync(FULLM, ji, src);
                if (bv < thresh) {
                    float pv = __shfl_up_sync(FULLM, kval, 1);
                    int   pj = __shfl_up_sync(FULLM, kidx, 1);
                    if (lane < KSEL && bv < kval) {
                        if (lane == 0 || bv >= pv) { kval = bv; kidx = bj; }
                        else                        { kval = pv; kidx = pj; }
                    }
                    thresh = __shfl_sync(FULLM, kval, KSEL - 1);
                }
            }
        }
    };

    loadTile(0, eA);
    for (int t = 0; t < ntiles; t += 2) {
        loadTile(t + 1, eB);
        phaseA(t, 0, eA);
        __syncthreads();
        phaseB(t, 0);
        if (t + 1 < ntiles) {
            loadTile(t + 2, eA);
            phaseA(t + 1, 1, eB);
            __syncthreads();
            phaseB(t + 1, 1);
        }
    }

    // -------- features for row (rowbase + w) --------
    const int row = rowbase + w;
    float wgt = 0.f, sel = 0.f;
    if (lane < KSEL) {
        float d2  = fmaxf(kval + na, 0.f);
        float sim = sqrtf(d2) + 0.001f;
        wgt = __expf(-sim);
        sel = rctx[(size_t)row * n + kidx];
    }
    float sw = wgt, ssw = sel * wgt, ss = sel, ss2 = sel * sel;
#pragma unroll
    for (int off = 16; off; off >>= 1) {
        sw  += __shfl_xor_sync(FULLM, sw,  off);
        ssw += __shfl_xor_sync(FULLM, ssw, off);
        ss  += __shfl_xor_sync(FULLM, ss,  off);
        ss2 += __shfl_xor_sync(FULLM, ss2, off);
    }
    if (lane == 0) {
        float f1 = sw;
        float f2 = ssw / sw;
        float var = (ss2 - ss * ss / (float)KSEL) / (float)(KSEL - 1);
        float f3 = sqrtf(fmaxf(var, 0.f));
        g_feats[row][0 + set] = f1;
        g_feats[row][2 + set] = f2;
        g_feats[row][4 + set] = f3;
    }
}

// ---------------------------------------------------------------------------
// Tiny MLP: feats[8] -> relu(64) -> (mean, std)
// ---------------------------------------------------------------------------
__global__ void mlp_kernel(const float* __restrict__ mean_in,
                           const float* __restrict__ std_in,
                           const float* __restrict__ W1,
                           const float* __restrict__ b1,
                           const float* __restrict__ Wm,
                           const float* __restrict__ bm,
                           const float* __restrict__ Ws,
                           const float* __restrict__ bs,
                           float* __restrict__ out, int Bn) {
    int r = blockIdx.x * blockDim.x + threadIdx.x;
    if (r >= Bn) return;
    float f[8];
#pragma unroll
    for (int i = 0; i < 6; i++) f[i] = g_feats[r][i];
    f[6] = mean_in[r];
    f[7] = std_in[r];
    float m = bm[0], sd = bs[0];
    for (int j = 0; j < HID; j++) {
        float h = b1[j];
#pragma unroll
        for (int i = 0; i < 8; i++) h = fmaf(f[i], W1[i * HID + j], h);
        h = fmaxf(h, 0.f);
        m  = fmaf(h, Wm[j], m);
        sd = fmaf(h, Ws[j], sd);
    }
    out[r]      = m;
    out[Bn + r] = sd;
}

// ---------------------------------------------------------------------------
extern "C" void kernel_launch(void* const* d_in, const int* in_sizes, int n_in,
                              void* d_out, int out_size) {
    const float* emb0    = (const float*)d_in[0];
    const float* emb1    = (const float*)d_in[1];
    const float* rctx0   = (const float*)d_in[2];
    const float* rctx1   = (const float*)d_in[3];
    const int*   idx0    = (const int*)  d_in[4];
    const int*   idx1    = (const int*)  d_in[5];
    const float* mean_in = (const float*)d_in[6];
    const float* std_in  = (const float*)d_in[7];
    const float* W1      = (const float*)d_in[8];
    const float* b1      = (const float*)d_in[9];
    const float* Wm      = (const float*)d_in[10];
    const float* bm      = (const float*)d_in[11];
    const float* Ws      = (const float*)d_in[12];
    const float* bs      = (const float*)d_in[13];

    int n  = in_sizes[0] / E_DIM;   // 50000
    int Bn = in_sizes[4];           // 512

    dim3 grid(Bn / G_ROWS, 2);
    knn_kernel<<<grid, 256>>>(emb0, emb1, rctx0, rctx1, idx0, idx1, n);

    mlp_kernel<<<(Bn + 255) / 256, 256>>>(mean_in, std_in, W1, b1, Wm, bm, Ws, bs,
                                          (float*)d_out, Bn);
}